// round 1
// baseline (speedup 1.0000x reference)
#include <cuda_runtime.h>

#define NCOLS 24576   // B*3*N = 4*3*2048
#define NPTS  2048
#define BATCH 4
#define KNN   20

// ---------------- static scratch (no allocation allowed) ----------------
__device__ float g_B1[256 * NCOLS];   // XIN0 / NET ping
__device__ float g_B2[256 * NCOLS];   // D0 / D1
__device__ float g_B3[256 * NCOLS];   // Y / Y2
__device__ float g_B4[128 * NCOLS];   // H
__device__ float g_B5[128 * NCOLS];   // NET pong
__device__ float g_mean[BATCH * NPTS * 3];
__device__ float g_pool[256 * 12];
__device__ float g_Pd0[256 * 12];
__device__ float g_PWs[128 * 12];

// ---------------- KNN mean: one block per query point ----------------
__global__ __launch_bounds__(256) void knn_mean_kernel(const float* __restrict__ p,
                                                       float* __restrict__ outm) {
    __shared__ float sx[NPTS], sy[NPTS], sz[NPTS], sxx[NPTS], sd[NPTS];
    __shared__ float wv[8];
    __shared__ int   wi[8];
    int bid = blockIdx.x;
    int b = bid >> 11, n = bid & 2047;
    int tid = threadIdx.x;
    const float* pb = p + b * NPTS * 3;
    for (int i = tid; i < NPTS; i += 256) {
        float x = pb[i*3+0], y = pb[i*3+1], z = pb[i*3+2];
        sx[i] = x; sy[i] = y; sz[i] = z;
        sxx[i] = x*x + y*y + z*z;
    }
    __syncthreads();
    float qx = sx[n], qy = sy[n], qz = sz[n], qq = sxx[n];
    for (int i = tid; i < NPTS; i += 256)
        sd[i] = 2.f * (qx*sx[i] + qy*sy[i] + qz*sz[i]) - qq - sxx[i];
    __syncthreads();
    float ax = 0.f, ay = 0.f, az = 0.f;
    for (int r = 0; r < KNN; r++) {
        float bv = -3.4e38f; int bi = 1 << 30;
        for (int i = tid; i < NPTS; i += 256) {
            float v = sd[i];
            if (v > bv) { bv = v; bi = i; }   // ascending scan -> smallest idx wins ties
        }
        for (int off = 16; off; off >>= 1) {
            float ov = __shfl_down_sync(0xffffffffu, bv, off);
            int   oi = __shfl_down_sync(0xffffffffu, bi, off);
            if (ov > bv || (ov == bv && oi < bi)) { bv = ov; bi = oi; }
        }
        if ((tid & 31) == 0) { wv[tid >> 5] = bv; wi[tid >> 5] = bi; }
        __syncthreads();
        if (tid == 0) {
            float best = wv[0]; int bj = wi[0];
            for (int w = 1; w < 8; w++)
                if (wv[w] > best || (wv[w] == best && wi[w] < bj)) { best = wv[w]; bj = wi[w]; }
            ax += sx[bj]; ay += sy[bj]; az += sz[bj];
            sd[bj] = -3.4e38f;
        }
        __syncthreads();
    }
    if (tid == 0) {
        const float inv = 1.f / KNN;
        outm[bid*3+0] = ax * inv;
        outm[bid*3+1] = ay * inv;
        outm[bid*3+2] = az * inv;
    }
}

// ------------- fused graph-feature * fc_pos, mean over k -------------
// out[o, col] with col=(b,v,n); uses only m (knn mean) and p.
__global__ __launch_bounds__(256) void feat_kernel(const float* __restrict__ p,
                                                   const float* __restrict__ m,
                                                   const float* __restrict__ W,
                                                   float* __restrict__ out) {
    int idx = blockIdx.x * 256 + threadIdx.x;       // < 256*NCOLS
    int o = idx / NCOLS;
    int col = idx - o * NCOLS;
    int b = col / 6144;
    int rem = col - b * 6144;
    int v = rem >> 11;
    int n = rem & 2047;
    int pi = (b * NPTS + n) * 3;
    float px = p[pi], py = p[pi+1], pz = p[pi+2];
    float mx = m[pi], my = m[pi+1], mz = m[pi+2];
    float pv, mv, cv;
    if (v == 0)      { pv = px; mv = mx; cv = my*pz - mz*py; }
    else if (v == 1) { pv = py; mv = my; cv = mz*px - mx*pz; }
    else             { pv = pz; mv = mz; cv = mx*py - my*px; }
    float w0 = W[o*3+0], w1 = W[o*3+1], w2 = W[o*3+2];
    out[idx] = w0 * (mv - pv) + w1 * pv + w2 * cv;
}

// ---------------- SGEMM: C[M,NCOLS] = A[M,K](lda) @ B[K,NCOLS] (+bias)(+=C) ----------------
// BM=128, BN=64, BK=16, 256 threads, 8x4 per thread.
__global__ __launch_bounds__(256) void sgemm(const float* __restrict__ A, int lda,
                                             const float* __restrict__ B,
                                             float* __restrict__ C, int K,
                                             const float* __restrict__ bias, int accum) {
    __shared__ float As[16][128];
    __shared__ float Bs[16][64];
    int tid = threadIdx.x;
    int tx = tid & 15;
    int ty = tid >> 4;
    const float* Ab = A + blockIdx.y * 128 * lda;
    const float* Bb = B + blockIdx.x * 64;
    float acc[8][4];
#pragma unroll
    for (int i = 0; i < 8; i++)
#pragma unroll
        for (int j = 0; j < 4; j++) acc[i][j] = 0.f;

    for (int kt = 0; kt < K; kt += 16) {
#pragma unroll
        for (int l = 0; l < 2; l++) {
            int i = tid + l * 256;            // 0..511 float4s of the 128x16 A tile
            int row = i >> 2;
            int c4 = (i & 3) << 2;
            float4 a = *(const float4*)(Ab + row * lda + kt + c4);
            As[c4+0][row] = a.x; As[c4+1][row] = a.y;
            As[c4+2][row] = a.z; As[c4+3][row] = a.w;
        }
        {
            int row = tid >> 4;
            int c4 = (tid & 15) << 2;
            float4 bb = *(const float4*)(Bb + (kt + row) * NCOLS + c4);
            *(float4*)&Bs[row][c4] = bb;
        }
        __syncthreads();
#pragma unroll
        for (int kk = 0; kk < 16; kk++) {
            float4 a0 = *(const float4*)&As[kk][ty*8];
            float4 a1 = *(const float4*)&As[kk][ty*8+4];
            float4 b0 = *(const float4*)&Bs[kk][tx*4];
            float av[8] = {a0.x, a0.y, a0.z, a0.w, a1.x, a1.y, a1.z, a1.w};
            float bv[4] = {b0.x, b0.y, b0.z, b0.w};
#pragma unroll
            for (int i = 0; i < 8; i++)
#pragma unroll
                for (int j = 0; j < 4; j++) acc[i][j] += av[i] * bv[j];
        }
        __syncthreads();
    }
    int colBase = blockIdx.x * 64 + tx * 4;
    int bvIdx = colBase >> 11;   // (b*3+v) index, constant within a 64-wide tile
#pragma unroll
    for (int i = 0; i < 8; i++) {
        int row = blockIdx.y * 128 + ty * 8 + i;
        float4 r;
        r.x = acc[i][0]; r.y = acc[i][1]; r.z = acc[i][2]; r.w = acc[i][3];
        if (bias) {
            float bb = bias[row * 12 + bvIdx];
            r.x += bb; r.y += bb; r.z += bb; r.w += bb;
        }
        float* Cp = C + row * NCOLS + colBase;
        if (accum) {
            float4 o = *(const float4*)Cp;
            r.x += o.x; r.y += o.y; r.z += o.z; r.w += o.w;
        }
        *(float4*)Cp = r;
    }
}

// ---------------- VN leaky-relu (slope 0) ----------------
// Rows >=128 read X from the broadcast pooled buffer when Xpool != null.
__global__ __launch_bounds__(256) void vnrelu(const float* __restrict__ X,
                                              const float* __restrict__ Xpool,
                                              const float* __restrict__ D,
                                              float* __restrict__ Y, int M) {
    int idx = blockIdx.x * 256 + threadIdx.x;
    if (idx >= M * 8192) return;
    int o = idx >> 13;
    int r = idx & 8191;
    int b = r >> 11, n = r & 2047;
    int base = o * NCOLS + b * 6144 + n;
    float x0, x1, x2;
    if (Xpool != nullptr && o >= 128) {
        int pb = (o - 128) * 12 + b * 3;
        x0 = Xpool[pb]; x1 = Xpool[pb+1]; x2 = Xpool[pb+2];
    } else {
        x0 = X[base]; x1 = X[base+2048]; x2 = X[base+4096];
    }
    float d0 = D[base], d1 = D[base+2048], d2 = D[base+4096];
    float dot = x0*d0 + x1*d1 + x2*d2;
    float dsq = d0*d0 + d1*d1 + d2*d2 + 1e-8f;
    float t = (dot >= 0.f) ? 0.f : dot / dsq;
    Y[base]      = x0 - t*d0;
    Y[base+2048] = x1 - t*d1;
    Y[base+4096] = x2 - t*d2;
}

// ---------------- mean over N: out[c*12 + (b*3+v)] ----------------
__global__ __launch_bounds__(256) void poolk(const float* __restrict__ NET,
                                             float* __restrict__ out) {
    int c = blockIdx.x / 12, bv = blockIdx.x % 12;
    const float* row = NET + c * NCOLS + bv * 2048;
    int tid = threadIdx.x;
    float s = 0.f;
    for (int n = tid; n < 2048; n += 256) s += row[n];
    for (int off = 16; off; off >>= 1) s += __shfl_down_sync(0xffffffffu, s, off);
    __shared__ float ws[8];
    if ((tid & 31) == 0) ws[tid >> 5] = s;
    __syncthreads();
    if (tid == 0) {
        float t = 0.f;
        for (int w = 0; w < 8; w++) t += ws[w];
        out[c * 12 + bv] = t * (1.f / 2048.f);
    }
}

// ---------------- tiny rank-12 projection: out[o,bv] = A[o,128:256] @ pooled ----------------
__global__ __launch_bounds__(256) void pooled_proj(const float* __restrict__ A, int lda,
                                                   const float* __restrict__ pl,
                                                   float* __restrict__ out, int M) {
    int idx = blockIdx.x * 256 + threadIdx.x;
    if (idx >= M * 12) return;
    int o = idx / 12, bv = idx - o * 12;
    const float* Ar = A + o * lda + 128;
    float s = 0.f;
    for (int c = 0; c < 128; c++) s += Ar[c] * pl[c * 12 + bv];
    out[idx] = s;
}

// ---------------- final head: relu(act_d) + fc_c on [128,12] ----------------
__global__ __launch_bounds__(512) void final_head(const float* __restrict__ PF,
                                                  const float* __restrict__ act_d,
                                                  const float* __restrict__ fc_c,
                                                  float* __restrict__ out) {
    __shared__ float spf[1536], sd[1536], sy[1536];
    int tid = threadIdx.x;
    for (int i = tid; i < 1536; i += 512) spf[i] = PF[i];
    __syncthreads();
    for (int i = tid; i < 1536; i += 512) {
        int o = i / 12, bv = i - o * 12;
        float s = 0.f;
        for (int c = 0; c < 128; c++) s += act_d[o*128 + c] * spf[c*12 + bv];
        sd[i] = s;
    }
    __syncthreads();
    {   // 512 threads == 128*4 (o,b) pairs
        int o = tid >> 2, b = tid & 3;
        int base = o * 12 + b * 3;
        float x0 = spf[base], x1 = spf[base+1], x2 = spf[base+2];
        float d0 = sd[base],  d1 = sd[base+1],  d2 = sd[base+2];
        float dot = x0*d0 + x1*d1 + x2*d2;
        float dsq = d0*d0 + d1*d1 + d2*d2 + 1e-8f;
        float t = (dot >= 0.f) ? 0.f : dot / dsq;
        sy[base]   = x0 - t*d0;
        sy[base+1] = x1 - t*d1;
        sy[base+2] = x2 - t*d2;
    }
    __syncthreads();
    for (int i = tid; i < 1536; i += 512) {
        int o = i / 12, bv = i - o * 12;
        int b = bv / 3, v = bv - b * 3;
        float s = 0.f;
        for (int c = 0; c < 128; c++) s += fc_c[o*128 + c] * sy[c*12 + bv];
        out[b * 384 + o * 3 + v] = s;
    }
}

// ---------------- launcher ----------------
extern "C" void kernel_launch(void* const* d_in, const int* in_sizes, int n_in,
                              void* d_out, int out_size) {
    const float* p        = (const float*)d_in[0];
    const float* fc_pos_W = (const float*)d_in[1];
    const float* blk_d0   = (const float*)d_in[2];   // [5,256,256]
    const float* blk_W0   = (const float*)d_in[3];   // [5,128,256]
    const float* blk_d1   = (const float*)d_in[4];   // [5,128,128]
    const float* blk_W1   = (const float*)d_in[5];   // [5,128,128]
    const float* blk_Ws   = (const float*)d_in[6];   // [5,128,256]
    const float* fc_c_W   = (const float*)d_in[7];   // [128,128]
    const float* act_d    = (const float*)d_in[8];   // [128,128]
    float* out = (float*)d_out;

    float *B1, *B2, *B3, *B4, *B5, *MEAN, *POOL, *PD0, *PWS;
    cudaGetSymbolAddress((void**)&B1, g_B1);
    cudaGetSymbolAddress((void**)&B2, g_B2);
    cudaGetSymbolAddress((void**)&B3, g_B3);
    cudaGetSymbolAddress((void**)&B4, g_B4);
    cudaGetSymbolAddress((void**)&B5, g_B5);
    cudaGetSymbolAddress((void**)&MEAN, g_mean);
    cudaGetSymbolAddress((void**)&POOL, g_pool);
    cudaGetSymbolAddress((void**)&PD0, g_Pd0);
    cudaGetSymbolAddress((void**)&PWS, g_PWs);

    const dim3 G1(384, 1), G2(384, 2);

    // front-end
    knn_mean_kernel<<<BATCH * NPTS, 256>>>(p, MEAN);
    feat_kernel<<<(256 * NCOLS) / 256, 256>>>(p, MEAN, fc_pos_W, B1);   // XIN0 [256]

    // ---- block 0 (input = XIN0, K=256, no pooled split) ----
    sgemm<<<G2, 256>>>(blk_d0, 256, B1, B2, 256, nullptr, 0);           // D0
    vnrelu<<<(256 * 8192) / 256, 256>>>(B1, nullptr, B2, B3, 256);      // Y
    sgemm<<<G1, 256>>>(blk_W0, 256, B3, B4, 256, nullptr, 0);           // H
    sgemm<<<G1, 256>>>(blk_d1, 128, B4, B2, 128, nullptr, 0);           // D1
    vnrelu<<<(128 * 8192) / 256, 256>>>(B4, nullptr, B2, B3, 128);      // Y2
    sgemm<<<G1, 256>>>(blk_Ws, 256, B1, B5, 256, nullptr, 0);           // NET = Ws@XIN0
    sgemm<<<G1, 256>>>(blk_W1, 128, B3, B5, 128, nullptr, 1);           // NET += W1@Y2

    // ---- blocks 1..4: concat handled as (varying half GEMM + rank-12 bias) ----
    float* NETin = B5;
    float* NETout = B1;
    for (int i = 1; i < 5; i++) {
        const float* d0w = blk_d0 + i * 65536;
        const float* W0w = blk_W0 + i * 32768;
        const float* d1w = blk_d1 + i * 16384;
        const float* W1w = blk_W1 + i * 16384;
        const float* Wsw = blk_Ws + i * 32768;

        poolk<<<128 * 12, 256>>>(NETin, POOL);
        pooled_proj<<<12, 256>>>(d0w, 256, POOL, PD0, 256);
        pooled_proj<<<6, 256>>>(Wsw, 256, POOL, PWS, 128);

        sgemm<<<G2, 256>>>(d0w, 256, NETin, B2, 128, PD0, 0);           // D0 full (256 rows)
        vnrelu<<<(256 * 8192) / 256, 256>>>(NETin, POOL, B2, B3, 256);  // Y (rows>=128 use pooled x)
        sgemm<<<G1, 256>>>(W0w, 256, B3, B4, 256, nullptr, 0);          // H
        sgemm<<<G1, 256>>>(d1w, 128, B4, B2, 128, nullptr, 0);          // D1
        vnrelu<<<(128 * 8192) / 256, 256>>>(B4, nullptr, B2, B3, 128);  // Y2
        sgemm<<<G1, 256>>>(Wsw, 256, NETin, NETout, 128, PWS, 0);       // NET' = Ws[:, :128]@NET + PWs
        sgemm<<<G1, 256>>>(W1w, 128, B3, NETout, 128, nullptr, 1);      // NET' += W1@Y2

        float* t = NETin; NETin = NETout; NETout = t;
    }

    // ---- final pooling + head ----
    poolk<<<128 * 12, 256>>>(NETin, POOL);
    final_head<<<1, 512>>>(POOL, act_d, fc_c_W, out);
}

// round 2
// speedup vs baseline: 1.1544x; 1.1544x over previous
#include <cuda_runtime.h>
#include <cuda_bf16.h>
#include <cstdint>

#define NCOLS 24576   // B*3*N = 4*3*2048
#define NPTS  2048
#define BATCH 4
#define KNN   20

// ---------------- static scratch ----------------
__device__ float g_NETf0[256 * NCOLS];
__device__ float g_NETf1[256 * NCOLS];
__device__ float g_Df[256 * NCOLS];
__device__ float g_Hf[128 * NCOLS];
__device__ __nv_bfloat16 g_XN0h[256 * NCOLS], g_XN0l[256 * NCOLS];
__device__ __nv_bfloat16 g_XN1h[256 * NCOLS], g_XN1l[256 * NCOLS];
__device__ __nv_bfloat16 g_Yh[256 * NCOLS],  g_Yl[256 * NCOLS];
__device__ __nv_bfloat16 g_Hh[128 * NCOLS],  g_Hl[128 * NCOLS];
__device__ __nv_bfloat16 g_Y2h[128 * NCOLS], g_Y2l[128 * NCOLS];
__device__ __nv_bfloat16 g_Wh[819200], g_Wl[819200];
__device__ float g_mean[BATCH * NPTS * 3];
__device__ float g_pool[256 * 12];
__device__ float g_Pd0[256 * 12];
__device__ float g_PWs[128 * 12];

// weight-split region offsets
#define OFF_D0 0
#define OFF_W0 327680
#define OFF_D1 491520
#define OFF_W1 573440
#define OFF_WS 655360

// ---------------- ptx helpers ----------------
__device__ __forceinline__ void cpa16(uint32_t dst, const void* src) {
    asm volatile("cp.async.cg.shared.global [%0], [%1], 16;\n" :: "r"(dst), "l"(src));
}
__device__ __forceinline__ void ldsm4(uint32_t* r, uint32_t addr) {
    asm volatile("ldmatrix.sync.aligned.m8n8.x4.shared.b16 {%0,%1,%2,%3}, [%4];"
                 : "=r"(r[0]), "=r"(r[1]), "=r"(r[2]), "=r"(r[3]) : "r"(addr));
}
__device__ __forceinline__ void ldsm4t(uint32_t* r, uint32_t addr) {
    asm volatile("ldmatrix.sync.aligned.m8n8.x4.trans.shared.b16 {%0,%1,%2,%3}, [%4];"
                 : "=r"(r[0]), "=r"(r[1]), "=r"(r[2]), "=r"(r[3]) : "r"(addr));
}
__device__ __forceinline__ void mma16816(float* c, const uint32_t* a, const uint32_t* b) {
    asm volatile("mma.sync.aligned.m16n8k16.row.col.f32.bf16.bf16.f32 "
                 "{%0,%1,%2,%3}, {%4,%5,%6,%7}, {%8,%9}, {%0,%1,%2,%3};"
                 : "+f"(c[0]), "+f"(c[1]), "+f"(c[2]), "+f"(c[3])
                 : "r"(a[0]), "r"(a[1]), "r"(a[2]), "r"(a[3]), "r"(b[0]), "r"(b[1]));
}

// ---------------- weight split fp32 -> bf16 hi/lo ----------------
__global__ __launch_bounds__(256) void splitw(const float* __restrict__ src,
                                              __nv_bfloat16* __restrict__ h,
                                              __nv_bfloat16* __restrict__ l, int n) {
    int i = blockIdx.x * 256 + threadIdx.x;
    if (i < n) {
        float x = src[i];
        __nv_bfloat16 hh = __float2bfloat16(x);
        h[i] = hh;
        l[i] = __float2bfloat16(x - __bfloat162float(hh));
    }
}

// ---------------- KNN mean ----------------
__global__ __launch_bounds__(256) void knn_mean_kernel(const float* __restrict__ p,
                                                       float* __restrict__ outm) {
    __shared__ float sx[NPTS], sy[NPTS], sz[NPTS], sxx[NPTS], sd[NPTS];
    __shared__ float wv[8];
    __shared__ int   wi[8];
    int bid = blockIdx.x;
    int b = bid >> 11, n = bid & 2047;
    int tid = threadIdx.x;
    const float* pb = p + b * NPTS * 3;
    for (int i = tid; i < NPTS; i += 256) {
        float x = pb[i*3+0], y = pb[i*3+1], z = pb[i*3+2];
        sx[i] = x; sy[i] = y; sz[i] = z;
        sxx[i] = x*x + y*y + z*z;
    }
    __syncthreads();
    float qx = sx[n], qy = sy[n], qz = sz[n], qq = sxx[n];
    for (int i = tid; i < NPTS; i += 256)
        sd[i] = 2.f * (qx*sx[i] + qy*sy[i] + qz*sz[i]) - qq - sxx[i];
    __syncthreads();
    float ax = 0.f, ay = 0.f, az = 0.f;
    for (int r = 0; r < KNN; r++) {
        float bv = -3.4e38f; int bi = 1 << 30;
        for (int i = tid; i < NPTS; i += 256) {
            float v = sd[i];
            if (v > bv) { bv = v; bi = i; }
        }
        for (int off = 16; off; off >>= 1) {
            float ov = __shfl_down_sync(0xffffffffu, bv, off);
            int   oi = __shfl_down_sync(0xffffffffu, bi, off);
            if (ov > bv || (ov == bv && oi < bi)) { bv = ov; bi = oi; }
        }
        if ((tid & 31) == 0) { wv[tid >> 5] = bv; wi[tid >> 5] = bi; }
        __syncthreads();
        if (tid == 0) {
            float best = wv[0]; int bj = wi[0];
            for (int w = 1; w < 8; w++)
                if (wv[w] > best || (wv[w] == best && wi[w] < bj)) { best = wv[w]; bj = wi[w]; }
            ax += sx[bj]; ay += sy[bj]; az += sz[bj];
            sd[bj] = -3.4e38f;
        }
        __syncthreads();
    }
    if (tid == 0) {
        const float inv = 1.f / KNN;
        outm[bid*3+0] = ax * inv;
        outm[bid*3+1] = ay * inv;
        outm[bid*3+2] = az * inv;
    }
}

// ------------- fused graph-feature * fc_pos, mean over k; writes fp32 + bf16 hi/lo -------------
__global__ __launch_bounds__(256) void feat_kernel(const float* __restrict__ p,
                                                   const float* __restrict__ m,
                                                   const float* __restrict__ W,
                                                   float* __restrict__ out,
                                                   __nv_bfloat16* __restrict__ oh,
                                                   __nv_bfloat16* __restrict__ ol) {
    int idx = blockIdx.x * 256 + threadIdx.x;
    int o = idx / NCOLS;
    int col = idx - o * NCOLS;
    int b = col / 6144;
    int rem = col - b * 6144;
    int v = rem >> 11;
    int n = rem & 2047;
    int pi = (b * NPTS + n) * 3;
    float px = p[pi], py = p[pi+1], pz = p[pi+2];
    float mx = m[pi], my = m[pi+1], mz = m[pi+2];
    float pv, mv, cv;
    if (v == 0)      { pv = px; mv = mx; cv = my*pz - mz*py; }
    else if (v == 1) { pv = py; mv = my; cv = mz*px - mx*pz; }
    else             { pv = pz; mv = mz; cv = mx*py - my*px; }
    float w0 = W[o*3+0], w1 = W[o*3+1], w2 = W[o*3+2];
    float r = w0 * (mv - pv) + w1 * pv + w2 * cv;
    out[idx] = r;
    __nv_bfloat16 h = __float2bfloat16(r);
    oh[idx] = h;
    ol[idx] = __float2bfloat16(r - __bfloat162float(h));
}

// ---------------- split-bf16 tensor-core GEMM ----------------
// C[M,NCOLS] = A[M,K](lda) @ B[K,NCOLS], A/B given as bf16 hi/lo splits.
// BM=128, BN=32, BK=16, 256 threads (8 warps, warp tile 16x32), cp.async double buffer.
#define AS_OFF(s,hl) (((s)*2 + (hl)) * 6144)
#define BS_OFF(s,hl) (24576 + ((s)*2 + (hl)) * 1280)

__global__ __launch_bounds__(256) void bgemm(
    const __nv_bfloat16* __restrict__ Ah, const __nv_bfloat16* __restrict__ Al,
    int lda, int K,
    const __nv_bfloat16* __restrict__ Bh, const __nv_bfloat16* __restrict__ Bl,
    float* __restrict__ C,
    __nv_bfloat16* __restrict__ Ch, __nv_bfloat16* __restrict__ Cl,
    const float* __restrict__ bias, int accum)
{
    __shared__ __align__(16) unsigned char smem[24576 + 5120];
    uint32_t smBase = (uint32_t)__cvta_generic_to_shared(smem);
    int tid = threadIdx.x;
    int lane = tid & 31, w = tid >> 5;
    int mblk = blockIdx.y * 128;
    int nb = blockIdx.x * 32;

    float acc[4][4];
#pragma unroll
    for (int i = 0; i < 4; i++)
#pragma unroll
        for (int j = 0; j < 4; j++) acc[i][j] = 0.f;

    int KT = K >> 4;

    auto load_stage = [&](int s, int kt) {
        int kt16 = kt << 4;
        {
            int r = tid >> 1, c = (tid & 1) << 3;
            cpa16(smBase + AS_OFF(s,0) + (uint32_t)(r*24 + c)*2, Ah + (mblk + r)*lda + kt16 + c);
            cpa16(smBase + AS_OFF(s,1) + (uint32_t)(r*24 + c)*2, Al + (mblk + r)*lda + kt16 + c);
        }
        if (tid < 64) {
            int r = tid >> 2, c = (tid & 3) << 3;
            cpa16(smBase + BS_OFF(s,0) + (uint32_t)(r*40 + c)*2, Bh + (kt16 + r)*NCOLS + nb + c);
        } else if (tid < 128) {
            int t = tid - 64;
            int r = t >> 2, c = (t & 3) << 3;
            cpa16(smBase + BS_OFF(s,1) + (uint32_t)(r*40 + c)*2, Bl + (kt16 + r)*NCOLS + nb + c);
        }
    };

    load_stage(0, 0);
    asm volatile("cp.async.commit_group;\n" ::);

    for (int it = 0; it < KT; it++) {
        int s = it & 1;
        if (it + 1 < KT) {
            load_stage(1 - s, it + 1);
            asm volatile("cp.async.commit_group;\n" ::);
            asm volatile("cp.async.wait_group 1;\n" ::);
        } else {
            asm volatile("cp.async.wait_group 0;\n" ::);
        }
        __syncthreads();

        uint32_t aH[4], aL[4];
        uint32_t abase = (uint32_t)((w*16 + (lane & 15))*24 + ((lane >> 4) << 3)) * 2;
        ldsm4(aH, smBase + AS_OFF(s,0) + abase);
        ldsm4(aL, smBase + AS_OFF(s,1) + abase);

        uint32_t bH[4][2], bL[4][2];
#pragma unroll
        for (int half = 0; half < 2; half++) {
            uint32_t bbase = (uint32_t)((lane & 15)*40 + half*16 + ((lane >> 4) << 3)) * 2;
            uint32_t t4[4];
            ldsm4t(t4, smBase + BS_OFF(s,0) + bbase);
            bH[half*2][0] = t4[0]; bH[half*2][1] = t4[1];
            bH[half*2+1][0] = t4[2]; bH[half*2+1][1] = t4[3];
            ldsm4t(t4, smBase + BS_OFF(s,1) + bbase);
            bL[half*2][0] = t4[0]; bL[half*2][1] = t4[1];
            bL[half*2+1][0] = t4[2]; bL[half*2+1][1] = t4[3];
        }
#pragma unroll
        for (int nt = 0; nt < 4; nt++) {
            mma16816(acc[nt], aH, bH[nt]);
            mma16816(acc[nt], aH, bL[nt]);
            mma16816(acc[nt], aL, bH[nt]);
        }
        __syncthreads();
    }

    // epilogue
    int r0 = mblk + w*16 + (lane >> 2);
    int c0 = nb + ((lane & 3) << 1);
    int bv = c0 >> 11;
    float bb0 = 0.f, bb1 = 0.f;
    if (bias) { bb0 = bias[r0*12 + bv]; bb1 = bias[(r0+8)*12 + bv]; }
#pragma unroll
    for (int nt = 0; nt < 4; nt++) {
        int col = c0 + nt*8;
        float v00 = acc[nt][0] + bb0, v01 = acc[nt][1] + bb0;
        float v10 = acc[nt][2] + bb1, v11 = acc[nt][3] + bb1;
        size_t i0 = (size_t)r0 * NCOLS + col;
        size_t i1 = i0 + (size_t)8 * NCOLS;
        if (accum) {
            float2 o0 = *(const float2*)(C + i0);
            float2 o1 = *(const float2*)(C + i1);
            v00 += o0.x; v01 += o0.y; v10 += o1.x; v11 += o1.y;
        }
        if (C) {
            float2 s0; s0.x = v00; s0.y = v01;
            float2 s1; s1.x = v10; s1.y = v11;
            *(float2*)(C + i0) = s0;
            *(float2*)(C + i1) = s1;
        }
        if (Ch) {
            __nv_bfloat16 h00 = __float2bfloat16(v00), h01 = __float2bfloat16(v01);
            __nv_bfloat16 h10 = __float2bfloat16(v10), h11 = __float2bfloat16(v11);
            *(__nv_bfloat162*)(Ch + i0) = __halves2bfloat162(h00, h01);
            *(__nv_bfloat162*)(Ch + i1) = __halves2bfloat162(h10, h11);
            *(__nv_bfloat162*)(Cl + i0) = __halves2bfloat162(
                __float2bfloat16(v00 - __bfloat162float(h00)),
                __float2bfloat16(v01 - __bfloat162float(h01)));
            *(__nv_bfloat162*)(Cl + i1) = __halves2bfloat162(
                __float2bfloat16(v10 - __bfloat162float(h10)),
                __float2bfloat16(v11 - __bfloat162float(h11)));
        }
    }
}

// ---------------- VN leaky-relu (slope 0), float4 per thread, bf16 hi/lo output ----------------
__global__ __launch_bounds__(256) void vnrelu4(const float* __restrict__ X,
                                               const float* __restrict__ Xpool,
                                               const float* __restrict__ D,
                                               __nv_bfloat16* __restrict__ Yh,
                                               __nv_bfloat16* __restrict__ Yl, int M) {
    int idx = blockIdx.x * 256 + threadIdx.x;     // M * 2048 threads
    int o = idx >> 11;
    if (o >= M) return;
    int r = idx & 2047;
    int b = r >> 9;
    int n = (r & 511) << 2;
    int base = o * NCOLS + b * 6144 + n;

    float4 d0 = *(const float4*)(D + base);
    float4 d1 = *(const float4*)(D + base + 2048);
    float4 d2 = *(const float4*)(D + base + 4096);
    float4 x0, x1, x2;
    if (Xpool != nullptr && o >= 128) {
        int pb = (o - 128) * 12 + b * 3;
        float s0 = Xpool[pb], s1 = Xpool[pb+1], s2 = Xpool[pb+2];
        x0.x = x0.y = x0.z = x0.w = s0;
        x1.x = x1.y = x1.z = x1.w = s1;
        x2.x = x2.y = x2.z = x2.w = s2;
    } else {
        x0 = *(const float4*)(X + base);
        x1 = *(const float4*)(X + base + 2048);
        x2 = *(const float4*)(X + base + 4096);
    }
    float xs0[4] = {x0.x, x0.y, x0.z, x0.w};
    float xs1[4] = {x1.x, x1.y, x1.z, x1.w};
    float xs2[4] = {x2.x, x2.y, x2.z, x2.w};
    float ds0[4] = {d0.x, d0.y, d0.z, d0.w};
    float ds1[4] = {d1.x, d1.y, d1.z, d1.w};
    float ds2[4] = {d2.x, d2.y, d2.z, d2.w};
    float y0[4], y1[4], y2[4];
#pragma unroll
    for (int j = 0; j < 4; j++) {
        float dot = xs0[j]*ds0[j] + xs1[j]*ds1[j] + xs2[j]*ds2[j];
        float dsq = ds0[j]*ds0[j] + ds1[j]*ds1[j] + ds2[j]*ds2[j] + 1e-8f;
        float t = (dot >= 0.f) ? 0.f : dot / dsq;
        y0[j] = xs0[j] - t*ds0[j];
        y1[j] = xs1[j] - t*ds1[j];
        y2[j] = xs2[j] - t*ds2[j];
    }
#pragma unroll
    for (int v = 0; v < 3; v++) {
        const float* yy = (v == 0) ? y0 : (v == 1) ? y1 : y2;
        int off = base + v * 2048;
        __nv_bfloat16 h0 = __float2bfloat16(yy[0]), h1 = __float2bfloat16(yy[1]);
        __nv_bfloat16 h2 = __float2bfloat16(yy[2]), h3 = __float2bfloat16(yy[3]);
        *(__nv_bfloat162*)(Yh + off)     = __halves2bfloat162(h0, h1);
        *(__nv_bfloat162*)(Yh + off + 2) = __halves2bfloat162(h2, h3);
        *(__nv_bfloat162*)(Yl + off)     = __halves2bfloat162(
            __float2bfloat16(yy[0] - __bfloat162float(h0)),
            __float2bfloat16(yy[1] - __bfloat162float(h1)));
        *(__nv_bfloat162*)(Yl + off + 2) = __halves2bfloat162(
            __float2bfloat16(yy[2] - __bfloat162float(h2)),
            __float2bfloat16(yy[3] - __bfloat162float(h3)));
    }
}

// ---------------- mean over N ----------------
__global__ __launch_bounds__(256) void poolk(const float* __restrict__ NET,
                                             float* __restrict__ out) {
    int c = blockIdx.x / 12, bv = blockIdx.x % 12;
    const float* row = NET + c * NCOLS + bv * 2048;
    int tid = threadIdx.x;
    float s = 0.f;
    for (int n = tid; n < 2048; n += 256) s += row[n];
    for (int off = 16; off; off >>= 1) s += __shfl_down_sync(0xffffffffu, s, off);
    __shared__ float ws[8];
    if ((tid & 31) == 0) ws[tid >> 5] = s;
    __syncthreads();
    if (tid == 0) {
        float t = 0.f;
        for (int w = 0; w < 8; w++) t += ws[w];
        out[c * 12 + bv] = t * (1.f / 2048.f);
    }
}

// ---------------- tiny rank-12 projection ----------------
__global__ __launch_bounds__(256) void pooled_proj(const float* __restrict__ A, int lda,
                                                   const float* __restrict__ pl,
                                                   float* __restrict__ out, int M) {
    int idx = blockIdx.x * 256 + threadIdx.x;
    if (idx >= M * 12) return;
    int o = idx / 12, bv = idx - o * 12;
    const float* Ar = A + o * lda + 128;
    float s = 0.f;
    for (int c = 0; c < 128; c++) s += Ar[c] * pl[c * 12 + bv];
    out[idx] = s;
}

// ---------------- final head ----------------
__global__ __launch_bounds__(512) void final_head(const float* __restrict__ PF,
                                                  const float* __restrict__ act_d,
                                                  const float* __restrict__ fc_c,
                                                  float* __restrict__ out) {
    __shared__ float spf[1536], sd[1536], sy[1536];
    int tid = threadIdx.x;
    for (int i = tid; i < 1536; i += 512) spf[i] = PF[i];
    __syncthreads();
    for (int i = tid; i < 1536; i += 512) {
        int o = i / 12, bv = i - o * 12;
        float s = 0.f;
        for (int c = 0; c < 128; c++) s += act_d[o*128 + c] * spf[c*12 + bv];
        sd[i] = s;
    }
    __syncthreads();
    {
        int o = tid >> 2, b = tid & 3;
        int base = o * 12 + b * 3;
        float x0 = spf[base], x1 = spf[base+1], x2 = spf[base+2];
        float d0 = sd[base],  d1 = sd[base+1],  d2 = sd[base+2];
        float dot = x0*d0 + x1*d1 + x2*d2;
        float dsq = d0*d0 + d1*d1 + d2*d2 + 1e-8f;
        float t = (dot >= 0.f) ? 0.f : dot / dsq;
        sy[base]   = x0 - t*d0;
        sy[base+1] = x1 - t*d1;
        sy[base+2] = x2 - t*d2;
    }
    __syncthreads();
    for (int i = tid; i < 1536; i += 512) {
        int o = i / 12, bv = i - o * 12;
        int b = bv / 3, v = bv - b * 3;
        float s = 0.f;
        for (int c = 0; c < 128; c++) s += fc_c[o*128 + c] * sy[c*12 + bv];
        out[b * 384 + o * 3 + v] = s;
    }
}

// ---------------- launcher ----------------
extern "C" void kernel_launch(void* const* d_in, const int* in_sizes, int n_in,
                              void* d_out, int out_size) {
    const float* p        = (const float*)d_in[0];
    const float* fc_pos_W = (const float*)d_in[1];
    const float* blk_d0   = (const float*)d_in[2];
    const float* blk_W0   = (const float*)d_in[3];
    const float* blk_d1   = (const float*)d_in[4];
    const float* blk_W1   = (const float*)d_in[5];
    const float* blk_Ws   = (const float*)d_in[6];
    const float* fc_c_W   = (const float*)d_in[7];
    const float* act_d    = (const float*)d_in[8];
    float* out = (float*)d_out;

    float *NETf0, *NETf1, *Df, *Hf, *MEAN, *POOL, *PD0, *PWS;
    __nv_bfloat16 *XN0h, *XN0l, *XN1h, *XN1l, *Yh, *Yl, *Hh, *Hl, *Y2h, *Y2l, *Wh, *Wl;
    cudaGetSymbolAddress((void**)&NETf0, g_NETf0);
    cudaGetSymbolAddress((void**)&NETf1, g_NETf1);
    cudaGetSymbolAddress((void**)&Df, g_Df);
    cudaGetSymbolAddress((void**)&Hf, g_Hf);
    cudaGetSymbolAddress((void**)&MEAN, g_mean);
    cudaGetSymbolAddress((void**)&POOL, g_pool);
    cudaGetSymbolAddress((void**)&PD0, g_Pd0);
    cudaGetSymbolAddress((void**)&PWS, g_PWs);
    cudaGetSymbolAddress((void**)&XN0h, g_XN0h);
    cudaGetSymbolAddress((void**)&XN0l, g_XN0l);
    cudaGetSymbolAddress((void**)&XN1h, g_XN1h);
    cudaGetSymbolAddress((void**)&XN1l, g_XN1l);
    cudaGetSymbolAddress((void**)&Yh, g_Yh);
    cudaGetSymbolAddress((void**)&Yl, g_Yl);
    cudaGetSymbolAddress((void**)&Hh, g_Hh);
    cudaGetSymbolAddress((void**)&Hl, g_Hl);
    cudaGetSymbolAddress((void**)&Y2h, g_Y2h);
    cudaGetSymbolAddress((void**)&Y2l, g_Y2l);
    cudaGetSymbolAddress((void**)&Wh, g_Wh);
    cudaGetSymbolAddress((void**)&Wl, g_Wl);

    // weight splits
    splitw<<<(327680 + 255) / 256, 256>>>(blk_d0, Wh + OFF_D0, Wl + OFF_D0, 327680);
    splitw<<<(163840 + 255) / 256, 256>>>(blk_W0, Wh + OFF_W0, Wl + OFF_W0, 163840);
    splitw<<<(81920  + 255) / 256, 256>>>(blk_d1, Wh + OFF_D1, Wl + OFF_D1, 81920);
    splitw<<<(81920  + 255) / 256, 256>>>(blk_W1, Wh + OFF_W1, Wl + OFF_W1, 81920);
    splitw<<<(163840 + 255) / 256, 256>>>(blk_Ws, Wh + OFF_WS, Wl + OFF_WS, 163840);

    // front-end
    knn_mean_kernel<<<BATCH * NPTS, 256>>>(p, MEAN);
    feat_kernel<<<(256 * NCOLS) / 256, 256>>>(p, MEAN, fc_pos_W, NETf0, XN0h, XN0l);

    const dim3 G1(768, 1), G2(768, 2);

    // ---- block 0 (input XIN0 in NETf0/XN0, K=256) ----
    bgemm<<<G2, 256>>>(Wh+OFF_D0, Wl+OFF_D0, 256, 256, XN0h, XN0l, Df, nullptr, nullptr, nullptr, 0);
    vnrelu4<<<256 * 8, 256>>>(NETf0, nullptr, Df, Yh, Yl, 256);
    bgemm<<<G1, 256>>>(Wh+OFF_W0, Wl+OFF_W0, 256, 256, Yh, Yl, Hf, Hh, Hl, nullptr, 0);
    bgemm<<<G1, 256>>>(Wh+OFF_D1, Wl+OFF_D1, 128, 128, Hh, Hl, Df, nullptr, nullptr, nullptr, 0);
    vnrelu4<<<128 * 8, 256>>>(Hf, nullptr, Df, Y2h, Y2l, 128);
    bgemm<<<G1, 256>>>(Wh+OFF_WS, Wl+OFF_WS, 256, 256, XN0h, XN0l, NETf1, nullptr, nullptr, nullptr, 0);
    bgemm<<<G1, 256>>>(Wh+OFF_W1, Wl+OFF_W1, 128, 128, Y2h, Y2l, NETf1, XN1h, XN1l, nullptr, 1);

    // ---- blocks 1..4 ----
    float* NETin = NETf1;  __nv_bfloat16 *NINh = XN1h, *NINl = XN1l;
    float* NETout = NETf0; __nv_bfloat16 *NOh = XN0h,  *NOl = XN0l;
    for (int i = 1; i < 5; i++) {
        poolk<<<128 * 12, 256>>>(NETin, POOL);
        pooled_proj<<<12, 256>>>(blk_d0 + i * 65536, 256, POOL, PD0, 256);
        pooled_proj<<<6, 256>>>(blk_Ws + i * 32768, 256, POOL, PWS, 128);

        bgemm<<<G2, 256>>>(Wh+OFF_D0+i*65536, Wl+OFF_D0+i*65536, 256, 128, NINh, NINl, Df, nullptr, nullptr, PD0, 0);
        vnrelu4<<<256 * 8, 256>>>(NETin, POOL, Df, Yh, Yl, 256);
        bgemm<<<G1, 256>>>(Wh+OFF_W0+i*32768, Wl+OFF_W0+i*32768, 256, 256, Yh, Yl, Hf, Hh, Hl, nullptr, 0);
        bgemm<<<G1, 256>>>(Wh+OFF_D1+i*16384, Wl+OFF_D1+i*16384, 128, 128, Hh, Hl, Df, nullptr, nullptr, nullptr, 0);
        vnrelu4<<<128 * 8, 256>>>(Hf, nullptr, Df, Y2h, Y2l, 128);
        bgemm<<<G1, 256>>>(Wh+OFF_WS+i*32768, Wl+OFF_WS+i*32768, 256, 128, NINh, NINl, NETout, nullptr, nullptr, PWS, 0);
        bgemm<<<G1, 256>>>(Wh+OFF_W1+i*16384, Wl+OFF_W1+i*16384, 128, 128, Y2h, Y2l, NETout, NOh, NOl, nullptr, 1);

        float* tf = NETin; NETin = NETout; NETout = tf;
        __nv_bfloat16* tb;
        tb = NINh; NINh = NOh; NOh = tb;
        tb = NINl; NINl = NOl; NOl = tb;
    }

    // ---- final pooling + head ----
    poolk<<<128 * 12, 256>>>(NETin, POOL);
    final_head<<<1, 512>>>(POOL, act_d, fc_c_W, out);
}